// round 8
// baseline (speedup 1.0000x reference)
#include <cuda_runtime.h>
#include <cuda_bf16.h>
#include <cstdint>

// ---------------------------------------------------------------------------
// Problem constants
//   x  [2, 2048, 1024] f32
//   Wq/Wk/Wv [1024,1024] f32 (row-major, [k][n]),  bq/bk/bv [1024]
//   out [2, 2048, 1024] f32   = causal MHA, 16 heads, head_dim 64,
//   softmax((QK^T + mask)/8)
// ---------------------------------------------------------------------------

#define NHEADS 16
#define HDIM   64
#define SEQ    2048
#define BATCH  2
#define DMODEL 1024

// Scratch: Q/K/V in [B, H, S, Dh] layout (16 MB each)
__device__ float g_q[BATCH * NHEADS * SEQ * HDIM];
__device__ float g_k[BATCH * NHEADS * SEQ * HDIM];
__device__ float g_v[BATCH * NHEADS * SEQ * HDIM];

// ---------------------------------------------------------------------------
// tf32 helpers (mma.sync.m16n8k8.tf32 fragment layouts, PTX ISA 9.7.13.4.x)
//   A(16x8,row): a0=(g,tig) a1=(g+8,tig) a2=(g,tig+4) a3=(g+8,tig+4)
//   B(8x8,col):  b0=(tig,g) b1=(tig+4,g)      [row = k, col = n]
//   C(16x8):     c0=(g,2t) c1=(g,2t+1) c2=(g+8,2t) c3=(g+8,2t+1)
// ---------------------------------------------------------------------------
__device__ __forceinline__ unsigned f2tf(float x) {
    unsigned r;
    asm("cvt.rna.tf32.f32 %0, %1;" : "=r"(r) : "f"(x));
    return r;
}

__device__ __forceinline__ void split_tf32(float v, unsigned& hi, unsigned& lo) {
    unsigned h;
    asm("cvt.rna.tf32.f32 %0, %1;" : "=r"(h) : "f"(v));
    float rem = v - __uint_as_float(h);
    unsigned l;
    asm("cvt.rna.tf32.f32 %0, %1;" : "=r"(l) : "f"(rem));
    hi = h; lo = l;
}

__device__ __forceinline__ void mma8(float& d0, float& d1, float& d2, float& d3,
                                     unsigned a0, unsigned a1, unsigned a2, unsigned a3,
                                     unsigned b0, unsigned b1) {
    asm("mma.sync.aligned.m16n8k8.row.col.f32.tf32.tf32.f32 "
        "{%0,%1,%2,%3},{%4,%5,%6,%7},{%8,%9},{%0,%1,%2,%3};"
        : "+f"(d0), "+f"(d1), "+f"(d2), "+f"(d3)
        : "r"(a0), "r"(a1), "r"(a2), "r"(a3), "r"(b0), "r"(b1));
}

// ---------------------------------------------------------------------------
// Kernel 1: fused QKV projection GEMM with 3xTF32 split (near-fp32 accuracy)
//   grid (48, 32): x = mat*16 + ntile  (mat: 0=Q,1=K,2=V; 16 n-tiles of 64)
//                  y = m-tile of 128 over M = B*S = 4096
//   block 256 (8 warps, 4(M) x 2(N), each warp 32x32 of the 128x64 tile)
// ---------------------------------------------------------------------------
#define GA_STR 36   // A smem row stride (words): bank = (4g+tig) -> conflict-free
#define GB_STR 72   // B smem row stride (words): bank = (8tig+g) -> conflict-free

__global__ __launch_bounds__(256, 2)
void qkv_kernel(const float* __restrict__ x,
                const float* __restrict__ Wq, const float* __restrict__ Wk,
                const float* __restrict__ Wv,
                const float* __restrict__ bq, const float* __restrict__ bk,
                const float* __restrict__ bv) {
    __shared__ float As[128 * GA_STR];
    __shared__ float Bs[32 * GB_STR];

    const int tid  = threadIdx.x;
    const int wid  = tid >> 5;
    const int lane = tid & 31;
    const int g    = lane >> 2;
    const int tig  = lane & 3;

    const int mat = blockIdx.x >> 4;
    const int n0  = (blockIdx.x & 15) * 64;
    const int m0  = blockIdx.y * 128;

    const float* W    = (mat == 0) ? Wq : ((mat == 1) ? Wk : Wv);
    const float* bias = (mat == 0) ? bq : ((mat == 1) ? bk : bv);
    float* dst        = (mat == 0) ? g_q : ((mat == 1) ? g_k : g_v);

    const int warpM = (wid & 3) * 32;
    const int warpN = (wid >> 2) * 32;

    float acc[2][4][4];
#pragma unroll
    for (int mt = 0; mt < 2; mt++)
#pragma unroll
        for (int nt = 0; nt < 4; nt++)
#pragma unroll
            for (int j = 0; j < 4; j++) acc[mt][nt][j] = 0.f;

    for (int k0 = 0; k0 < DMODEL; k0 += 32) {
        // stage A tile 128x32 (4 float4/thread) and B tile 32x64 (2 float4/thread)
#pragma unroll
        for (int i = 0; i < 4; i++) {
            int id = tid + i * 256;
            int r = id >> 3, c = id & 7;
            *(float4*)(As + r * GA_STR + c * 4) =
                *(const float4*)(x + (size_t)(m0 + r) * DMODEL + k0 + c * 4);
        }
#pragma unroll
        for (int i = 0; i < 2; i++) {
            int id = tid + i * 256;
            int r = id >> 4, c = id & 15;
            *(float4*)(Bs + r * GB_STR + c * 4) =
                *(const float4*)(W + (size_t)(k0 + r) * DMODEL + n0 + c * 4);
        }
        __syncthreads();

#pragma unroll
        for (int kk = 0; kk < 4; kk++) {
            const int kb = kk * 8;
            unsigned ah[2][4], al[2][4];
#pragma unroll
            for (int mt = 0; mt < 2; mt++) {
                int rb = warpM + mt * 16 + g;
                split_tf32(As[rb * GA_STR + kb + tig],           ah[mt][0], al[mt][0]);
                split_tf32(As[(rb + 8) * GA_STR + kb + tig],     ah[mt][1], al[mt][1]);
                split_tf32(As[rb * GA_STR + kb + tig + 4],       ah[mt][2], al[mt][2]);
                split_tf32(As[(rb + 8) * GA_STR + kb + tig + 4], ah[mt][3], al[mt][3]);
            }
            unsigned bh[4][2], bl[4][2];
#pragma unroll
            for (int nt = 0; nt < 4; nt++) {
                int col = warpN + nt * 8 + g;
                split_tf32(Bs[(kb + tig) * GB_STR + col],     bh[nt][0], bl[nt][0]);
                split_tf32(Bs[(kb + tig + 4) * GB_STR + col], bh[nt][1], bl[nt][1]);
            }
#pragma unroll
            for (int mt = 0; mt < 2; mt++)
#pragma unroll
                for (int nt = 0; nt < 4; nt++) {
                    mma8(acc[mt][nt][0], acc[mt][nt][1], acc[mt][nt][2], acc[mt][nt][3],
                         ah[mt][0], ah[mt][1], ah[mt][2], ah[mt][3], bh[nt][0], bh[nt][1]);
                    mma8(acc[mt][nt][0], acc[mt][nt][1], acc[mt][nt][2], acc[mt][nt][3],
                         al[mt][0], al[mt][1], al[mt][2], al[mt][3], bh[nt][0], bh[nt][1]);
                    mma8(acc[mt][nt][0], acc[mt][nt][1], acc[mt][nt][2], acc[mt][nt][3],
                         ah[mt][0], ah[mt][1], ah[mt][2], ah[mt][3], bl[nt][0], bl[nt][1]);
                }
        }
        __syncthreads();
    }

    // Epilogue: +bias, scatter to [B,H,S,Dh]
#pragma unroll
    for (int mt = 0; mt < 2; mt++) {
        int r0 = m0 + warpM + mt * 16 + g;
        int r1 = r0 + 8;
        int bb = r0 >> 11;
        int s0 = r0 & 2047, s1 = r1 & 2047;
#pragma unroll
        for (int nt = 0; nt < 4; nt++) {
            int col = n0 + warpN + nt * 8 + tig * 2;
            float bv0 = bias[col], bv1 = bias[col + 1];
            int hh = col >> 6, dh = col & 63;
            size_t base = ((size_t)(bb * NHEADS + hh)) * SEQ;
            *(float2*)(dst + (base + s0) * HDIM + dh) =
                make_float2(acc[mt][nt][0] + bv0, acc[mt][nt][1] + bv1);
            *(float2*)(dst + (base + s1) * HDIM + dh) =
                make_float2(acc[mt][nt][2] + bv0, acc[mt][nt][3] + bv1);
        }
    }
}

// ---------------------------------------------------------------------------
// Kernel 2: causal flash attention, tf32 tensor cores
//   grid (16, 16, 2): x = q-tile (reversed: long tiles first), y = head, z = batch
//   block 256; warp w owns q-rows [w*16, w*16+16) across ALL 64 k-columns,
//   so softmax reductions are quad shuffles only.
// ---------------------------------------------------------------------------
#define QSTR 68  // Qs/Ps stride: A-frag bank = (4g+tig) conflict-free
#define KSTR 68  // Ks stride:    B-frag bank = (4g+tig) conflict-free
#define VSTR 72  // Vs stride:    B-frag bank = (8tig+g) conflict-free
#define ATT_SMEM_WORDS (128 * QSTR + 64 * KSTR + 64 * VSTR + 128 * QSTR)
#define ATT_SMEM_BYTES (ATT_SMEM_WORDS * 4)

__global__ __launch_bounds__(256, 2)
void attn_kernel(float* __restrict__ out) {
    extern __shared__ float smem[];
    float* Qs = smem;
    float* Ks = Qs + 128 * QSTR;
    float* Vs = Ks + 64 * KSTR;
    float* Ps = Vs + 64 * VSTR;

    const int tid  = threadIdx.x;
    const int wid  = tid >> 5;
    const int lane = tid & 31;
    const int g    = lane >> 2;
    const int tig  = lane & 3;

    const int b  = blockIdx.z;
    const int h  = blockIdx.y;
    const int qt = (int)gridDim.x - 1 - (int)blockIdx.x;  // long tiles first
    const int q0 = qt * 128;

    const size_t headoff = ((size_t)(b * NHEADS + h)) * SEQ * HDIM;
    const float* Qp = g_q + headoff;
    const float* Kp = g_k + headoff;
    const float* Vp = g_v + headoff;

    // stage Q tile 128x64
#pragma unroll
    for (int i = 0; i < 8; i++) {
        int id = tid + i * 256;
        int r = id >> 4, c = id & 15;
        *(float4*)(Qs + r * QSTR + c * 4) =
            *(const float4*)(Qp + (size_t)(q0 + r) * HDIM + c * 4);
    }

    float Oa[8][4];
#pragma unroll
    for (int nt = 0; nt < 8; nt++)
#pragma unroll
        for (int j = 0; j < 4; j++) Oa[nt][j] = 0.f;

    float mrow0 = -1e30f, mrow1 = -1e30f, lrow0 = 0.f, lrow1 = 0.f;
    const int rowbase = wid * 16;
    const int qrow0 = q0 + rowbase + g;
    const int qrow1 = qrow0 + 8;
    const int nkt = 2 * qt + 2;  // causal: only tiles intersecting the triangle

    for (int kt = 0; kt < nkt; kt++) {
        __syncthreads();
        const int kbase = kt * 64;
#pragma unroll
        for (int i = 0; i < 4; i++) {
            int id = tid + i * 256;
            int r = id >> 4, c = id & 15;
            *(float4*)(Ks + r * KSTR + c * 4) =
                *(const float4*)(Kp + (size_t)(kbase + r) * HDIM + c * 4);
            *(float4*)(Vs + r * VSTR + c * 4) =
                *(const float4*)(Vp + (size_t)(kbase + r) * HDIM + c * 4);
        }
        __syncthreads();

        // S = Q K^T  (reduce over Dh=64)
        float sacc[8][4];
#pragma unroll
        for (int nt = 0; nt < 8; nt++) {
            sacc[nt][0] = 0.f; sacc[nt][1] = 0.f; sacc[nt][2] = 0.f; sacc[nt][3] = 0.f;
        }
#pragma unroll
        for (int kk = 0; kk < 8; kk++) {
            const int kb = kk * 8;
            unsigned a0 = f2tf(Qs[(rowbase + g) * QSTR + kb + tig]);
            unsigned a1 = f2tf(Qs[(rowbase + 8 + g) * QSTR + kb + tig]);
            unsigned a2 = f2tf(Qs[(rowbase + g) * QSTR + kb + tig + 4]);
            unsigned a3 = f2tf(Qs[(rowbase + 8 + g) * QSTR + kb + tig + 4]);
#pragma unroll
            for (int nt = 0; nt < 8; nt++) {
                unsigned b0 = f2tf(Ks[(nt * 8 + g) * KSTR + kb + tig]);
                unsigned b1 = f2tf(Ks[(nt * 8 + g) * KSTR + kb + tig + 4]);
                mma8(sacc[nt][0], sacc[nt][1], sacc[nt][2], sacc[nt][3],
                     a0, a1, a2, a3, b0, b1);
            }
        }

        // logits = (S + causal_mask)/8, online softmax
        float rmax0 = -1e30f, rmax1 = -1e30f;
#pragma unroll
        for (int nt = 0; nt < 8; nt++) {
            int c0 = kbase + nt * 8 + tig * 2;
            float v0 = sacc[nt][0] * 0.125f + ((c0     > qrow0) ? -1.25e8f : 0.f);
            float v1 = sacc[nt][1] * 0.125f + ((c0 + 1 > qrow0) ? -1.25e8f : 0.f);
            float v2 = sacc[nt][2] * 0.125f + ((c0     > qrow1) ? -1.25e8f : 0.f);
            float v3 = sacc[nt][3] * 0.125f + ((c0 + 1 > qrow1) ? -1.25e8f : 0.f);
            sacc[nt][0] = v0; sacc[nt][1] = v1; sacc[nt][2] = v2; sacc[nt][3] = v3;
            rmax0 = fmaxf(rmax0, fmaxf(v0, v1));
            rmax1 = fmaxf(rmax1, fmaxf(v2, v3));
        }
        rmax0 = fmaxf(rmax0, __shfl_xor_sync(0xffffffffu, rmax0, 1));
        rmax0 = fmaxf(rmax0, __shfl_xor_sync(0xffffffffu, rmax0, 2));
        rmax1 = fmaxf(rmax1, __shfl_xor_sync(0xffffffffu, rmax1, 1));
        rmax1 = fmaxf(rmax1, __shfl_xor_sync(0xffffffffu, rmax1, 2));

        float mnew0 = fmaxf(mrow0, rmax0);
        float mnew1 = fmaxf(mrow1, rmax1);
        float alpha0 = __expf(mrow0 - mnew0);
        float alpha1 = __expf(mrow1 - mnew1);

        float rs0 = 0.f, rs1 = 0.f;
#pragma unroll
        for (int nt = 0; nt < 8; nt++) {
            float p0 = __expf(sacc[nt][0] - mnew0);
            float p1 = __expf(sacc[nt][1] - mnew0);
            float p2 = __expf(sacc[nt][2] - mnew1);
            float p3 = __expf(sacc[nt][3] - mnew1);
            rs0 += p0 + p1;
            rs1 += p2 + p3;
            *(float2*)(Ps + (rowbase + g) * QSTR + nt * 8 + tig * 2)     = make_float2(p0, p1);
            *(float2*)(Ps + (rowbase + 8 + g) * QSTR + nt * 8 + tig * 2) = make_float2(p2, p3);
            Oa[nt][0] *= alpha0; Oa[nt][1] *= alpha0;
            Oa[nt][2] *= alpha1; Oa[nt][3] *= alpha1;
        }
        rs0 += __shfl_xor_sync(0xffffffffu, rs0, 1);
        rs0 += __shfl_xor_sync(0xffffffffu, rs0, 2);
        rs1 += __shfl_xor_sync(0xffffffffu, rs1, 1);
        rs1 += __shfl_xor_sync(0xffffffffu, rs1, 2);
        lrow0 = lrow0 * alpha0 + rs0;
        lrow1 = lrow1 * alpha1 + rs1;
        mrow0 = mnew0; mrow1 = mnew1;

        __syncwarp();  // warp reads only its own P rows — no block sync needed

        // O += P V   (reduce over 64 k-positions)
#pragma unroll
        for (int kk = 0; kk < 8; kk++) {
            const int kb = kk * 8;
            unsigned a0 = f2tf(Ps[(rowbase + g) * QSTR + kb + tig]);
            unsigned a1 = f2tf(Ps[(rowbase + 8 + g) * QSTR + kb + tig]);
            unsigned a2 = f2tf(Ps[(rowbase + g) * QSTR + kb + tig + 4]);
            unsigned a3 = f2tf(Ps[(rowbase + 8 + g) * QSTR + kb + tig + 4]);
#pragma unroll
            for (int nt = 0; nt < 8; nt++) {
                unsigned b0 = f2tf(Vs[(kb + tig) * VSTR + nt * 8 + g]);
                unsigned b1 = f2tf(Vs[(kb + tig + 4) * VSTR + nt * 8 + g]);
                mma8(Oa[nt][0], Oa[nt][1], Oa[nt][2], Oa[nt][3],
                     a0, a1, a2, a3, b0, b1);
            }
        }
    }

    // normalize + store to [B,S,H*Dh]
    float inv0 = 1.f / lrow0;
    float inv1 = 1.f / lrow1;
    float* o0 = out + ((size_t)(b * SEQ + qrow0)) * DMODEL + h * HDIM;
    float* o1 = out + ((size_t)(b * SEQ + qrow1)) * DMODEL + h * HDIM;
#pragma unroll
    for (int nt = 0; nt < 8; nt++) {
        int dh = nt * 8 + tig * 2;
        *(float2*)(o0 + dh) = make_float2(Oa[nt][0] * inv0, Oa[nt][1] * inv0);
        *(float2*)(o1 + dh) = make_float2(Oa[nt][2] * inv1, Oa[nt][3] * inv1);
    }
}

// ---------------------------------------------------------------------------
// Launch
// ---------------------------------------------------------------------------
extern "C" void kernel_launch(void* const* d_in, const int* in_sizes, int n_in,
                              void* d_out, int out_size) {
    (void)in_sizes; (void)n_in; (void)out_size;
    const float* x  = (const float*)d_in[0];
    const float* Wq = (const float*)d_in[1];
    const float* bq = (const float*)d_in[2];
    const float* Wk = (const float*)d_in[3];
    const float* bk = (const float*)d_in[4];
    const float* Wv = (const float*)d_in[5];
    const float* bv = (const float*)d_in[6];
    float* out = (float*)d_out;

    dim3 gq(48, 32, 1);
    qkv_kernel<<<gq, 256>>>(x, Wq, Wk, Wv, bq, bk, bv);

    cudaFuncSetAttribute(attn_kernel, cudaFuncAttributeMaxDynamicSharedMemorySize,
                         ATT_SMEM_BYTES);
    dim3 ga(16, 16, 2);
    attn_kernel<<<ga, 256, ATT_SMEM_BYTES>>>(out);
}

// round 9
// speedup vs baseline: 1.4429x; 1.4429x over previous
#include <cuda_runtime.h>
#include <cuda_bf16.h>
#include <cstdint>

// ---------------------------------------------------------------------------
// Problem constants
//   x  [2, 2048, 1024] f32
//   Wq/Wk/Wv [1024,1024] f32 (row-major [k][n]),  bq/bk/bv [1024]
//   out [2, 2048, 1024] f32 = causal MHA, 16 heads, head_dim 64,
//   softmax((QK^T + mask)/8)
// ---------------------------------------------------------------------------

#define NHEADS 16
#define HDIM   64
#define SEQ    2048
#define BATCH  2
#define DMODEL 1024

// Scratch: Q/K/V in [B, H, S, Dh] layout (16 MB each)
__device__ float g_q[BATCH * NHEADS * SEQ * HDIM];
__device__ float g_k[BATCH * NHEADS * SEQ * HDIM];
__device__ float g_v[BATCH * NHEADS * SEQ * HDIM];

// ---------------------------------------------------------------------------
// tf32 helpers (mma.sync.m16n8k8.tf32 fragment layouts)
//   A(16x8,row): a0=(g,tig) a1=(g+8,tig) a2=(g,tig+4) a3=(g+8,tig+4)
//   B(8x8,col):  b0=(tig,g) b1=(tig+4,g)      [row = k, col = n]
//   C(16x8):     c0=(g,2t) c1=(g,2t+1) c2=(g+8,2t) c3=(g+8,2t+1)
//
// Column permutation within each 8-group: perm(d) = ((d&3)<<1)|(d>>2),
// i.e. [0,4,1,5,2,6,3,7]. Then the fragment pair (tig, tig+4) sits at
// adjacent words (2*tig, 2*tig+1) -> one LDS.64 per pair.
// ---------------------------------------------------------------------------
__device__ __forceinline__ unsigned f2tf(float x) {
    unsigned r;
    asm("cvt.rna.tf32.f32 %0, %1;" : "=r"(r) : "f"(x));
    return r;
}

__device__ __forceinline__ int permc(int d) {  // d in [0,8)
    return ((d & 3) << 1) | (d >> 2);
}

__device__ __forceinline__ void mma8(float& d0, float& d1, float& d2, float& d3,
                                     unsigned a0, unsigned a1, unsigned a2, unsigned a3,
                                     unsigned b0, unsigned b1) {
    asm("mma.sync.aligned.m16n8k8.row.col.f32.tf32.tf32.f32 "
        "{%0,%1,%2,%3},{%4,%5,%6,%7},{%8,%9},{%0,%1,%2,%3};"
        : "+f"(d0), "+f"(d1), "+f"(d2), "+f"(d3)
        : "r"(a0), "r"(a1), "r"(a2), "r"(a3), "r"(b0), "r"(b1));
}

// ---------------------------------------------------------------------------
// Kernel 1: fused QKV projection GEMM, plain tf32 (pre-converted at stage)
//   grid (48, 32): x = mat*16 + ntile  (mat: 0=Q,1=K,2=V; 16 n-tiles of 64)
//                  y = m-tile of 128 over M = B*S = 4096
//   block 256 (8 warps, 4(M) x 2(N), each warp 32x32 of the 128x64 tile)
// ---------------------------------------------------------------------------
#define GA_STR 40   // A stride (words), permuted cols: 8B-bank = 4g+tig, CF
#define GB_STR 72   // B stride (words): bank = 8tig+g, CF

__global__ __launch_bounds__(256, 2)
void qkv_kernel(const float* __restrict__ x,
                const float* __restrict__ Wq, const float* __restrict__ Wk,
                const float* __restrict__ Wv,
                const float* __restrict__ bq, const float* __restrict__ bk,
                const float* __restrict__ bv) {
    __shared__ unsigned As[128 * GA_STR];   // tf32 bits, permuted k-cols
    __shared__ unsigned Bs[32 * GB_STR];    // tf32 bits, [k][n]

    const int tid  = threadIdx.x;
    const int wid  = tid >> 5;
    const int lane = tid & 31;
    const int g    = lane >> 2;
    const int tig  = lane & 3;

    const int mat = blockIdx.x >> 4;
    const int n0  = (blockIdx.x & 15) * 64;
    const int m0  = blockIdx.y * 128;

    const float* W    = (mat == 0) ? Wq : ((mat == 1) ? Wk : Wv);
    const float* bias = (mat == 0) ? bq : ((mat == 1) ? bk : bv);
    float* dst        = (mat == 0) ? g_q : ((mat == 1) ? g_k : g_v);

    const int warpM = (wid & 3) * 32;
    const int warpN = (wid >> 2) * 32;

    float acc[2][4][4];
#pragma unroll
    for (int mt = 0; mt < 2; mt++)
#pragma unroll
        for (int nt = 0; nt < 4; nt++)
#pragma unroll
            for (int j = 0; j < 4; j++) acc[mt][nt][j] = 0.f;

    for (int k0 = 0; k0 < DMODEL; k0 += 32) {
        // stage A tile 128x32 (permuted cols, tf32) and B tile 32x64 (tf32)
#pragma unroll
        for (int i = 0; i < 4; i++) {
            int id = tid + i * 256;
            int r = id >> 3, c = id & 7;
            float4 v = *(const float4*)(x + (size_t)(m0 + r) * DMODEL + k0 + c * 4);
            int d0 = c * 4;
            unsigned* row = As + r * GA_STR;
            row[(d0 & ~7) + permc(d0 & 7)]             = f2tf(v.x);
            row[((d0 + 1) & ~7) + permc((d0 + 1) & 7)] = f2tf(v.y);
            row[((d0 + 2) & ~7) + permc((d0 + 2) & 7)] = f2tf(v.z);
            row[((d0 + 3) & ~7) + permc((d0 + 3) & 7)] = f2tf(v.w);
        }
#pragma unroll
        for (int i = 0; i < 2; i++) {
            int id = tid + i * 256;
            int r = id >> 4, c = id & 15;
            float4 v = *(const float4*)(W + (size_t)(k0 + r) * DMODEL + n0 + c * 4);
            uint4 u = make_uint4(f2tf(v.x), f2tf(v.y), f2tf(v.z), f2tf(v.w));
            *(uint4*)(Bs + r * GB_STR + c * 4) = u;
        }
        __syncthreads();

#pragma unroll
        for (int kk = 0; kk < 4; kk++) {
            const int kb = kk * 8;
            uint2 a02[2], a13[2];
#pragma unroll
            for (int mt = 0; mt < 2; mt++) {
                int rb = warpM + mt * 16 + g;
                a02[mt] = *(const uint2*)(As + rb * GA_STR + kb + 2 * tig);
                a13[mt] = *(const uint2*)(As + (rb + 8) * GA_STR + kb + 2 * tig);
            }
            unsigned b0[4], b1[4];
#pragma unroll
            for (int nt = 0; nt < 4; nt++) {
                int col = warpN + nt * 8 + g;
                b0[nt] = Bs[(kb + tig) * GB_STR + col];
                b1[nt] = Bs[(kb + tig + 4) * GB_STR + col];
            }
#pragma unroll
            for (int mt = 0; mt < 2; mt++)
#pragma unroll
                for (int nt = 0; nt < 4; nt++)
                    mma8(acc[mt][nt][0], acc[mt][nt][1], acc[mt][nt][2], acc[mt][nt][3],
                         a02[mt].x, a13[mt].x, a02[mt].y, a13[mt].y, b0[nt], b1[nt]);
        }
        __syncthreads();
    }

    // Epilogue: +bias, scatter to [B,H,S,Dh]
#pragma unroll
    for (int mt = 0; mt < 2; mt++) {
        int r0 = m0 + warpM + mt * 16 + g;
        int r1 = r0 + 8;
        int bb = r0 >> 11;
        int s0 = r0 & 2047, s1 = r1 & 2047;
#pragma unroll
        for (int nt = 0; nt < 4; nt++) {
            int col = n0 + warpN + nt * 8 + tig * 2;
            float bv0 = bias[col], bv1 = bias[col + 1];
            int hh = col >> 6, dh = col & 63;
            size_t base = ((size_t)(bb * NHEADS + hh)) * SEQ;
            *(float2*)(dst + (base + s0) * HDIM + dh) =
                make_float2(acc[mt][nt][0] + bv0, acc[mt][nt][1] + bv1);
            *(float2*)(dst + (base + s1) * HDIM + dh) =
                make_float2(acc[mt][nt][2] + bv0, acc[mt][nt][3] + bv1);
        }
    }
}

// ---------------------------------------------------------------------------
// Kernel 2: causal flash attention, tf32 tensor cores, pre-converted smem
//   grid (16, 16, 2): x = q-tile (reversed: long tiles first), y = head, z = batch
//   block 256; warp w owns q-rows [w*16, w*16+16) across ALL 64 k-columns,
//   so softmax reductions are quad shuffles only.
//   Qs/Ks/Ps use permuted k-columns -> LDS.64 fragment pair loads.
// ---------------------------------------------------------------------------
#define QSTR 72  // permuted cols; 8B-bank = 4g+tig -> CF for pair loads
#define KSTR 72
#define VSTR 72  // unpermuted; 4B-bank = 8tig+g -> CF
#define ATT_SMEM_WORDS (128 * QSTR + 64 * KSTR + 64 * VSTR + 128 * QSTR)
#define ATT_SMEM_BYTES (ATT_SMEM_WORDS * 4)

__global__ __launch_bounds__(256, 2)
void attn_kernel(float* __restrict__ out) {
    extern __shared__ unsigned smem[];
    unsigned* Qs = smem;                 // [128][QSTR] tf32, permuted cols
    unsigned* Ks = Qs + 128 * QSTR;      // [64][KSTR]  tf32, permuted cols
    unsigned* Vs = Ks + 64 * KSTR;       // [64][VSTR]  tf32, plain cols
    unsigned* Ps = Vs + 64 * VSTR;       // [128][QSTR] tf32, permuted cols

    const int tid  = threadIdx.x;
    const int wid  = tid >> 5;
    const int lane = tid & 31;
    const int g    = lane >> 2;
    const int tig  = lane & 3;

    const int b  = blockIdx.z;
    const int h  = blockIdx.y;
    const int qt = (int)gridDim.x - 1 - (int)blockIdx.x;  // long tiles first
    const int q0 = qt * 128;

    const size_t headoff = ((size_t)(b * NHEADS + h)) * SEQ * HDIM;
    const float* Qp = g_q + headoff;
    const float* Kp = g_k + headoff;
    const float* Vp = g_v + headoff;

    // stage Q tile 128x64, convert to tf32, permuted columns
#pragma unroll
    for (int i = 0; i < 8; i++) {
        int id = tid + i * 256;
        int r = id >> 4, c = id & 15;
        float4 v = *(const float4*)(Qp + (size_t)(q0 + r) * HDIM + c * 4);
        int d0 = c * 4;
        unsigned* row = Qs + r * QSTR;
        row[(d0 & ~7) + permc(d0 & 7)]             = f2tf(v.x);
        row[((d0 + 1) & ~7) + permc((d0 + 1) & 7)] = f2tf(v.y);
        row[((d0 + 2) & ~7) + permc((d0 + 2) & 7)] = f2tf(v.z);
        row[((d0 + 3) & ~7) + permc((d0 + 3) & 7)] = f2tf(v.w);
    }

    float Oa[8][4];
#pragma unroll
    for (int nt = 0; nt < 8; nt++)
#pragma unroll
        for (int j = 0; j < 4; j++) Oa[nt][j] = 0.f;

    float mrow0 = -1e30f, mrow1 = -1e30f, lrow0 = 0.f, lrow1 = 0.f;
    const int rowbase = wid * 16;
    const int qrow0 = q0 + rowbase + g;
    const int qrow1 = qrow0 + 8;
    const int nkt = 2 * qt + 2;  // causal: only tiles intersecting the triangle

    // P-store permuted column offsets for this thread
    const int pc0 = permc(2 * tig);      // where col (nt*8 + 2*tig)   lands
    const int pc1 = permc(2 * tig + 1);  // where col (nt*8 + 2*tig+1) lands

    for (int kt = 0; kt < nkt; kt++) {
        __syncthreads();
        const int kbase = kt * 64;
#pragma unroll
        for (int i = 0; i < 4; i++) {
            int id = tid + i * 256;
            int r = id >> 4, c = id & 15;
            float4 kv = *(const float4*)(Kp + (size_t)(kbase + r) * HDIM + c * 4);
            int d0 = c * 4;
            unsigned* krow = Ks + r * KSTR;
            krow[(d0 & ~7) + permc(d0 & 7)]             = f2tf(kv.x);
            krow[((d0 + 1) & ~7) + permc((d0 + 1) & 7)] = f2tf(kv.y);
            krow[((d0 + 2) & ~7) + permc((d0 + 2) & 7)] = f2tf(kv.z);
            krow[((d0 + 3) & ~7) + permc((d0 + 3) & 7)] = f2tf(kv.w);
            float4 vv = *(const float4*)(Vp + (size_t)(kbase + r) * HDIM + c * 4);
            *(uint4*)(Vs + r * VSTR + c * 4) =
                make_uint4(f2tf(vv.x), f2tf(vv.y), f2tf(vv.z), f2tf(vv.w));
        }
        __syncthreads();

        // S = Q K^T  (reduce over Dh=64)
        float sacc[8][4];
#pragma unroll
        for (int nt = 0; nt < 8; nt++) {
            sacc[nt][0] = 0.f; sacc[nt][1] = 0.f; sacc[nt][2] = 0.f; sacc[nt][3] = 0.f;
        }
#pragma unroll
        for (int kk = 0; kk < 8; kk++) {
            const int kb = kk * 8;
            uint2 a02 = *(const uint2*)(Qs + (rowbase + g) * QSTR + kb + 2 * tig);
            uint2 a13 = *(const uint2*)(Qs + (rowbase + 8 + g) * QSTR + kb + 2 * tig);
#pragma unroll
            for (int nt = 0; nt < 8; nt++) {
                uint2 bb = *(const uint2*)(Ks + (nt * 8 + g) * KSTR + kb + 2 * tig);
                mma8(sacc[nt][0], sacc[nt][1], sacc[nt][2], sacc[nt][3],
                     a02.x, a13.x, a02.y, a13.y, bb.x, bb.y);
            }
        }

        // logits = (S + causal_mask)/8, online softmax
        float rmax0 = -1e30f, rmax1 = -1e30f;
#pragma unroll
        for (int nt = 0; nt < 8; nt++) {
            int c0 = kbase + nt * 8 + tig * 2;
            float v0 = sacc[nt][0] * 0.125f + ((c0     > qrow0) ? -1.25e8f : 0.f);
            float v1 = sacc[nt][1] * 0.125f + ((c0 + 1 > qrow0) ? -1.25e8f : 0.f);
            float v2 = sacc[nt][2] * 0.125f + ((c0     > qrow1) ? -1.25e8f : 0.f);
            float v3 = sacc[nt][3] * 0.125f + ((c0 + 1 > qrow1) ? -1.25e8f : 0.f);
            sacc[nt][0] = v0; sacc[nt][1] = v1; sacc[nt][2] = v2; sacc[nt][3] = v3;
            rmax0 = fmaxf(rmax0, fmaxf(v0, v1));
            rmax1 = fmaxf(rmax1, fmaxf(v2, v3));
        }
        rmax0 = fmaxf(rmax0, __shfl_xor_sync(0xffffffffu, rmax0, 1));
        rmax0 = fmaxf(rmax0, __shfl_xor_sync(0xffffffffu, rmax0, 2));
        rmax1 = fmaxf(rmax1, __shfl_xor_sync(0xffffffffu, rmax1, 1));
        rmax1 = fmaxf(rmax1, __shfl_xor_sync(0xffffffffu, rmax1, 2));

        float mnew0 = fmaxf(mrow0, rmax0);
        float mnew1 = fmaxf(mrow1, rmax1);
        float alpha0 = __expf(mrow0 - mnew0);
        float alpha1 = __expf(mrow1 - mnew1);

        float rs0 = 0.f, rs1 = 0.f;
#pragma unroll
        for (int nt = 0; nt < 8; nt++) {
            float p0 = __expf(sacc[nt][0] - mnew0);
            float p1 = __expf(sacc[nt][1] - mnew0);
            float p2 = __expf(sacc[nt][2] - mnew1);
            float p3 = __expf(sacc[nt][3] - mnew1);
            rs0 += p0 + p1;
            rs1 += p2 + p3;
            unsigned* pr0 = Ps + (rowbase + g) * QSTR + nt * 8;
            unsigned* pr1 = Ps + (rowbase + 8 + g) * QSTR + nt * 8;
            pr0[pc0] = f2tf(p0);
            pr0[pc1] = f2tf(p1);
            pr1[pc0] = f2tf(p2);
            pr1[pc1] = f2tf(p3);
            Oa[nt][0] *= alpha0; Oa[nt][1] *= alpha0;
            Oa[nt][2] *= alpha1; Oa[nt][3] *= alpha1;
        }
        rs0 += __shfl_xor_sync(0xffffffffu, rs0, 1);
        rs0 += __shfl_xor_sync(0xffffffffu, rs0, 2);
        rs1 += __shfl_xor_sync(0xffffffffu, rs1, 1);
        rs1 += __shfl_xor_sync(0xffffffffu, rs1, 2);
        lrow0 = lrow0 * alpha0 + rs0;
        lrow1 = lrow1 * alpha1 + rs1;
        mrow0 = mnew0; mrow1 = mnew1;

        __syncwarp();  // warp reads only its own P rows — no block sync needed

        // O += P V   (reduce over 64 k-positions)
#pragma unroll
        for (int kk = 0; kk < 8; kk++) {
            const int kb = kk * 8;
            uint2 a02 = *(const uint2*)(Ps + (rowbase + g) * QSTR + kb + 2 * tig);
            uint2 a13 = *(const uint2*)(Ps + (rowbase + 8 + g) * QSTR + kb + 2 * tig);
#pragma unroll
            for (int nt = 0; nt < 8; nt++) {
                unsigned b0 = Vs[(kb + tig) * VSTR + nt * 8 + g];
                unsigned b1 = Vs[(kb + tig + 4) * VSTR + nt * 8 + g];
                mma8(Oa[nt][0], Oa[nt][1], Oa[nt][2], Oa[nt][3],
                     a02.x, a13.x, a02.y, a13.y, b0, b1);
            }
        }
    }

    // normalize + store to [B,S,H*Dh]
    float inv0 = 1.f / lrow0;
    float inv1 = 1.f / lrow1;
    float* o0 = out + ((size_t)(b * SEQ + qrow0)) * DMODEL + h * HDIM;
    float* o1 = out + ((size_t)(b * SEQ + qrow1)) * DMODEL + h * HDIM;
#pragma unroll
    for (int nt = 0; nt < 8; nt++) {
        int dh = nt * 8 + tig * 2;
        *(float2*)(o0 + dh) = make_float2(Oa[nt][0] * inv0, Oa[nt][1] * inv0);
        *(float2*)(o1 + dh) = make_float2(Oa[nt][2] * inv1, Oa[nt][3] * inv1);
    }
}

// ---------------------------------------------------------------------------
// Launch
// ---------------------------------------------------------------------------
extern "C" void kernel_launch(void* const* d_in, const int* in_sizes, int n_in,
                              void* d_out, int out_size) {
    (void)in_sizes; (void)n_in; (void)out_size;
    const float* x  = (const float*)d_in[0];
    const float* Wq = (const float*)d_in[1];
    const float* bq = (const float*)d_in[2];
    const float* Wk = (const float*)d_in[3];
    const float* bk = (const float*)d_in[4];
    const float* Wv = (const float*)d_in[5];
    const float* bv = (const float*)d_in[6];
    float* out = (float*)d_out;

    dim3 gq(48, 32, 1);
    qkv_kernel<<<gq, 256>>>(x, Wq, Wk, Wv, bq, bk, bv);

    cudaFuncSetAttribute(attn_kernel, cudaFuncAttributeMaxDynamicSharedMemorySize,
                         ATT_SMEM_BYTES);
    dim3 ga(16, 16, 2);
    attn_kernel<<<ga, 256, ATT_SMEM_BYTES>>>(out);
}

// round 10
// speedup vs baseline: 2.8044x; 1.9436x over previous
#include <cuda_runtime.h>
#include <cuda_fp16.h>
#include <cstdint>

// ---------------------------------------------------------------------------
//   x [2,2048,1024] f32, Wq/Wk/Wv [1024,1024] f32 ([k][n]), bq/bk/bv [1024]
//   out [2,2048,1024] f32 = causal MHA, 16 heads, head_dim 64,
//   softmax((QK^T + mask)/8)
// fp16 datapath: fp16 (10-bit mantissa) == tf32 precision for these ranges.
// ---------------------------------------------------------------------------

#define NHEADS 16
#define HDIM   64
#define SEQ    2048
#define BATCH  2
#define DMODEL 1024

// fp16 pair-packed scratch (word = __half2 = 2 consecutive elements)
__device__ unsigned g_xh[4096 * 512];            // x  [m][k-words], permuted groups
__device__ unsigned g_wt[3 * 1024 * 512];        // W^T [mat][n][k-words], permuted
__device__ unsigned g_qh[BATCH * NHEADS * SEQ * 32];  // [b,h,s][dh-words], permuted
__device__ unsigned g_kh[BATCH * NHEADS * SEQ * 32];  // permuted
__device__ unsigned g_vh[BATCH * NHEADS * SEQ * 32];  // plain (attn transposes)

// ---------------------------------------------------------------------------
// helpers
//   mma.m16n8k16 fp16 fragments, thread (g=lane>>2, tig=lane&3):
//   A row-major: a0=(g, 2tig..+1) a1=(g+8, 2tig..) a2=(g, 2tig+8..) a3=(g+8, 2tig+8..)
//     -> in pair-word units: words tig and tig+4 of each 8-word (16-elem) group.
//   B col-major: b0=(k 2tig..+1, n g) b1=(k 2tig+8.., n g) -> words tig, tig+4.
//   C: c0=(g,2tig) c1=(g,2tig+1) c2=(g+8,2tig) c3=(g+8,2tig+1)
//   Word permutation within 8-word group: [0,4,1,5,2,6,3,7] -> (tig,tig+4)
//   adjacent -> one LDS.64 per fragment pair.
// ---------------------------------------------------------------------------
__device__ __forceinline__ int permc(int w) {  // w in [0,8)
    return ((w & 3) << 1) | (w >> 2);
}

__device__ __forceinline__ unsigned packh2(float lo, float hi) {
    __half2 h = __floats2half2_rn(lo, hi);
    return *(unsigned*)&h;
}

__device__ __forceinline__ void mma16(float& d0, float& d1, float& d2, float& d3,
                                      unsigned a0, unsigned a1, unsigned a2, unsigned a3,
                                      unsigned b0, unsigned b1) {
    asm("mma.sync.aligned.m16n8k16.row.col.f32.f16.f16.f32 "
        "{%0,%1,%2,%3},{%4,%5,%6,%7},{%8,%9},{%0,%1,%2,%3};"
        : "+f"(d0), "+f"(d1), "+f"(d2), "+f"(d3)
        : "r"(a0), "r"(a1), "r"(a2), "r"(a3), "r"(b0), "r"(b1));
}

__device__ __forceinline__ void cp16(void* smem, const void* gmem) {
    unsigned s = (unsigned)__cvta_generic_to_shared(smem);
    asm volatile("cp.async.ca.shared.global [%0], [%1], 16;" :: "r"(s), "l"(gmem));
}
#define CP_COMMIT() asm volatile("cp.async.commit_group;" ::: "memory")

// ---------------------------------------------------------------------------
// Pre-pass: pack x -> fp16 pair-words, permuted within 16-elem groups
// ---------------------------------------------------------------------------
__global__ void pack_x_kernel(const float* __restrict__ x) {
    int idx = blockIdx.x * 256 + threadIdx.x;   // 262144 groups of 16 floats
    const float4* src = (const float4*)x + (size_t)idx * 4;
    float4 f0 = src[0], f1 = src[1], f2 = src[2], f3 = src[3];
    unsigned w0 = packh2(f0.x, f0.y), w1 = packh2(f0.z, f0.w);
    unsigned w2 = packh2(f1.x, f1.y), w3 = packh2(f1.z, f1.w);
    unsigned w4 = packh2(f2.x, f2.y), w5 = packh2(f2.z, f2.w);
    unsigned w6 = packh2(f3.x, f3.y), w7 = packh2(f3.z, f3.w);
    uint4* dst = (uint4*)(g_xh + (size_t)idx * 8);
    dst[0] = make_uint4(w0, w4, w1, w5);   // permuted order [0,4,1,5,2,6,3,7]
    dst[1] = make_uint4(w2, w6, w3, w7);
}

// Pre-pass: pack W^T -> g_wt[mat][n][k-words], pairs along k, permuted
__global__ void pack_w_kernel(const float* __restrict__ Wq,
                              const float* __restrict__ Wk,
                              const float* __restrict__ Wv) {
    int id  = blockIdx.x * 256 + threadIdx.x;   // 196608 = 3 * 1024n * 64grp
    int mat = id >> 16;
    int rem = id & 65535;
    int grp = rem >> 10;
    int n   = rem & 1023;
    const float* W = (mat == 0) ? Wq : ((mat == 1) ? Wk : Wv);
    int k0 = grp * 16;
    float f[16];
#pragma unroll
    for (int j = 0; j < 16; j++) f[j] = W[(size_t)(k0 + j) * DMODEL + n];
    unsigned w[8];
#pragma unroll
    for (int j = 0; j < 8; j++) w[j] = packh2(f[2 * j], f[2 * j + 1]);
    uint4* dst = (uint4*)(g_wt + ((size_t)mat << 19) + (size_t)n * 512 + grp * 8);
    dst[0] = make_uint4(w[0], w[4], w[1], w[5]);
    dst[1] = make_uint4(w[2], w[6], w[3], w[7]);
}

// ---------------------------------------------------------------------------
// Kernel 1: QKV projection, fp16 m16n8k16, cp.async double-buffered
//   grid (48, 32): x = mat*16 + ntile (BN=64), y = m-tile (BM=128), BK=32
//   8 warps 4(M)x2(N), warp tile 32x32
// ---------------------------------------------------------------------------
#define QA_STR 24   // 16 words + 8 pad: frag bank pattern (24g+2tig) CF
#define QB_STR 24

__global__ __launch_bounds__(256, 3)
void qkv_h(const float* __restrict__ bq, const float* __restrict__ bk,
           const float* __restrict__ bv) {
    __shared__ unsigned As[2][128 * QA_STR];
    __shared__ unsigned Bs[2][64 * QB_STR];

    const int tid  = threadIdx.x;
    const int wid  = tid >> 5;
    const int lane = tid & 31;
    const int g    = lane >> 2;
    const int tig  = lane & 3;

    const int mat = blockIdx.x >> 4;
    const int n0  = (blockIdx.x & 15) * 64;
    const int m0  = blockIdx.y * 128;

    const unsigned* Asrc = g_xh + (size_t)m0 * 512;
    const unsigned* Bsrc = g_wt + ((size_t)mat << 19) + (size_t)n0 * 512;
    const float* bias = (mat == 0) ? bq : ((mat == 1) ? bk : bv);

    const int warpM = (wid & 3) * 32;
    const int warpN = (wid >> 2) * 32;

    float acc[2][4][4];
#pragma unroll
    for (int mt = 0; mt < 2; mt++)
#pragma unroll
        for (int nt = 0; nt < 4; nt++)
#pragma unroll
            for (int j = 0; j < 4; j++) acc[mt][nt][j] = 0.f;

    const int ar0 = tid >> 2, ac0 = (tid & 3) * 4;
    const int ar1 = (tid + 256) >> 2, ac1 = ((tid + 256) & 3) * 4;

    // prologue: stage tile 0
    cp16(&As[0][ar0 * QA_STR + ac0], Asrc + (size_t)ar0 * 512 + ac0);
    cp16(&As[0][ar1 * QA_STR + ac1], Asrc + (size_t)ar1 * 512 + ac1);
    cp16(&Bs[0][ar0 * QB_STR + ac0], Bsrc + (size_t)ar0 * 512 + ac0);
    CP_COMMIT();

    for (int it = 0; it < 32; it++) {
        if (it < 31) {
            int buf = (it + 1) & 1, kw = (it + 1) * 16;
            cp16(&As[buf][ar0 * QA_STR + ac0], Asrc + (size_t)ar0 * 512 + kw + ac0);
            cp16(&As[buf][ar1 * QA_STR + ac1], Asrc + (size_t)ar1 * 512 + kw + ac1);
            cp16(&Bs[buf][ar0 * QB_STR + ac0], Bsrc + (size_t)ar0 * 512 + kw + ac0);
            CP_COMMIT();
            asm volatile("cp.async.wait_group 1;" ::: "memory");
        } else {
            asm volatile("cp.async.wait_group 0;" ::: "memory");
        }
        __syncthreads();

        const unsigned* A = As[it & 1];
        const unsigned* B = Bs[it & 1];
#pragma unroll
        for (int step = 0; step < 2; step++) {
            const int kb = step * 8;
            uint2 a02[2], a13[2];
#pragma unroll
            for (int mt = 0; mt < 2; mt++) {
                int row = warpM + mt * 16 + g;
                a02[mt] = *(const uint2*)(A + row * QA_STR + kb + 2 * tig);
                a13[mt] = *(const uint2*)(A + (row + 8) * QA_STR + kb + 2 * tig);
            }
            uint2 bb[4];
#pragma unroll
            for (int nt = 0; nt < 4; nt++)
                bb[nt] = *(const uint2*)(B + (warpN + nt * 8 + g) * QB_STR + kb + 2 * tig);
#pragma unroll
            for (int mt = 0; mt < 2; mt++)
#pragma unroll
                for (int nt = 0; nt < 4; nt++)
                    mma16(acc[mt][nt][0], acc[mt][nt][1], acc[mt][nt][2], acc[mt][nt][3],
                          a02[mt].x, a13[mt].x, a02[mt].y, a13[mt].y, bb[nt].x, bb[nt].y);
        }
        __syncthreads();
    }

    // epilogue: +bias, pack fp16 pairs, scatter to [B,H,S][dh-words]
    unsigned* dst = (mat == 0) ? g_qh : ((mat == 1) ? g_kh : g_vh);
    const bool doperm = (mat != 2);   // V stays plain (attn transposes it)
#pragma unroll
    for (int mt = 0; mt < 2; mt++) {
        int r0 = m0 + warpM + mt * 16 + g;
        int r1 = r0 + 8;
        int bb_ = r0 >> 11;
        int s0 = r0 & 2047, s1 = r1 & 2047;
#pragma unroll
        for (int nt = 0; nt < 4; nt++) {
            int col = n0 + warpN + nt * 8 + tig * 2;
            float bv0 = bias[col], bv1 = bias[col + 1];
            int w = (col & 63) >> 1;
            int pos = doperm ? ((w & ~7) | permc(w & 7)) : w;
            int hh = col >> 6;
            size_t base = (size_t)(bb_ * NHEADS + hh) * SEQ;
            dst[(base + s0) * 32 + pos] = packh2(acc[mt][nt][0] + bv0, acc[mt][nt][1] + bv1);
            dst[(base + s1) * 32 + pos] = packh2(acc[mt][nt][2] + bv0, acc[mt][nt][3] + bv1);
        }
    }
}

// ---------------------------------------------------------------------------
// Kernel 2: causal flash attention, fp16 m16n8k16
//   grid (16, 16, 2): x = q-tile (long first), y = head, z = batch; block 256
//   warp w owns q-rows [w*16, w*16+16) over all 64 k-cols.
//   Qs/Ks/Ps permuted pair-words; Vt = V transposed [dh][seq-words] permuted.
// ---------------------------------------------------------------------------
#define ASTR 40   // stride ≡ 8 mod 32 -> frag pattern (8g+2tig) conflict-free
#define ATT_SMEM_WORDS ((128 + 64 + 64 + 128) * ASTR)
#define ATT_SMEM_BYTES (ATT_SMEM_WORDS * 4)

__global__ __launch_bounds__(256, 2)
void attn_kernel(float* __restrict__ out) {
    extern __shared__ unsigned smem[];
    unsigned* Qs = smem;                 // [128][ASTR] permuted dh-pair words
    unsigned* Ks = Qs + 128 * ASTR;      // [64][ASTR]  permuted dh-pair words
    unsigned* Vt = Ks + 64 * ASTR;       // [64 dh][ASTR] permuted seq-pair words
    unsigned* Ps = Vt + 64 * ASTR;       // [128][ASTR] permuted k-pair words

    const int tid  = threadIdx.x;
    const int wid  = tid >> 5;
    const int lane = tid & 31;
    const int g    = lane >> 2;
    const int tig  = lane & 3;

    const int b  = blockIdx.z;
    const int h  = blockIdx.y;
    const int qt = (int)gridDim.x - 1 - (int)blockIdx.x;
    const int q0 = qt * 128;

    const size_t hw = (size_t)(b * NHEADS + h) * SEQ * 32;
    const unsigned* gq = g_qh + hw;
    const unsigned* gk = g_kh + hw;
    const unsigned* gv = g_vh + hw;

    // stage Q tile (already packed+permuted): straight uint4 copies
#pragma unroll
    for (int i = 0; i < 4; i++) {
        int idx = tid + i * 256;
        int r = idx >> 3, c = idx & 7;
        *(uint4*)(Qs + r * ASTR + c * 4) = *(const uint4*)(gq + (size_t)(q0 + r) * 32 + c * 4);
    }

    float Oa[8][4];
#pragma unroll
    for (int nt = 0; nt < 8; nt++)
#pragma unroll
        for (int j = 0; j < 4; j++) Oa[nt][j] = 0.f;

    float mrow0 = -1e30f, mrow1 = -1e30f, lrow0 = 0.f, lrow1 = 0.f;
    const int rowbase = wid * 16;
    const int qrow0 = q0 + rowbase + g;
    const int qrow1 = qrow0 + 8;
    const int nkt = 2 * qt + 2;

    const int vr = tid & 31;          // seq-pair index for V transpose staging
    const int vc = tid >> 5;          // dh quad
    const int vpos = (vr & ~7) | permc(vr & 7);

    for (int kt = 0; kt < nkt; kt++) {
        __syncthreads();
        const int kbase = kt * 64;
        // K: straight copies (packed+permuted in gmem)
#pragma unroll
        for (int i = 0; i < 2; i++) {
            int idx = tid + i * 256;
            int r = idx >> 3, c = idx & 7;
            *(uint4*)(Ks + r * ASTR + c * 4) =
                *(const uint4*)(gk + (size_t)(kbase + r) * 32 + c * 4);
        }
        // V: transpose into Vt[dh][seq-pair word] via byte_perm interleave
        {
            uint4 va = *(const uint4*)(gv + (size_t)(kbase + 2 * vr) * 32 + vc * 4);
            uint4 vb = *(const uint4*)(gv + (size_t)(kbase + 2 * vr + 1) * 32 + vc * 4);
            int d0 = vc * 8;
            Vt[(d0 + 0) * ASTR + vpos] = __byte_perm(va.x, vb.x, 0x5410);
            Vt[(d0 + 1) * ASTR + vpos] = __byte_perm(va.x, vb.x, 0x7632);
            Vt[(d0 + 2) * ASTR + vpos] = __byte_perm(va.y, vb.y, 0x5410);
            Vt[(d0 + 3) * ASTR + vpos] = __byte_perm(va.y, vb.y, 0x7632);
            Vt[(d0 + 4) * ASTR + vpos] = __byte_perm(va.z, vb.z, 0x5410);
            Vt[(d0 + 5) * ASTR + vpos] = __byte_perm(va.z, vb.z, 0x7632);
            Vt[(d0 + 6) * ASTR + vpos] = __byte_perm(va.w, vb.w, 0x5410);
            Vt[(d0 + 7) * ASTR + vpos] = __byte_perm(va.w, vb.w, 0x7632);
        }
        __syncthreads();

        // S = Q K^T (Dh=64 -> 4 k16 steps)
        float sacc[8][4];
#pragma unroll
        for (int nt = 0; nt < 8; nt++) {
            sacc[nt][0] = 0.f; sacc[nt][1] = 0.f; sacc[nt][2] = 0.f; sacc[nt][3] = 0.f;
        }
#pragma unroll
        for (int step = 0; step < 4; step++) {
            const int kb = step * 8;
            uint2 a02 = *(const uint2*)(Qs + (rowbase + g) * ASTR + kb + 2 * tig);
            uint2 a13 = *(const uint2*)(Qs + (rowbase + 8 + g) * ASTR + kb + 2 * tig);
#pragma unroll
            for (int nt = 0; nt < 8; nt++) {
                uint2 bb = *(const uint2*)(Ks + (nt * 8 + g) * ASTR + kb + 2 * tig);
                mma16(sacc[nt][0], sacc[nt][1], sacc[nt][2], sacc[nt][3],
                      a02.x, a13.x, a02.y, a13.y, bb.x, bb.y);
            }
        }

        // logits = (S + mask)/8, online softmax
        float rmax0 = -1e30f, rmax1 = -1e30f;
#pragma unroll
        for (int nt = 0; nt < 8; nt++) {
            int c0 = kbase + nt * 8 + tig * 2;
            float v0 = sacc[nt][0] * 0.125f + ((c0     > qrow0) ? -1.25e8f : 0.f);
            float v1 = sacc[nt][1] * 0.125f + ((c0 + 1 > qrow0) ? -1.25e8f : 0.f);
            float v2 = sacc[nt][2] * 0.125f + ((c0     > qrow1) ? -1.25e8f : 0.f);
            float v3 = sacc[nt][3] * 0.125f + ((c0 + 1 > qrow1) ? -1.25e8f : 0.f);
            sacc[nt][0] = v0; sacc[nt][1] = v1; sacc[nt][2] = v2; sacc[nt][3] = v3;
            rmax0 = fmaxf(rmax0, fmaxf(v0, v1));
            rmax1 = fmaxf(rmax1, fmaxf(v2, v3));
        }
        rmax0 = fmaxf(rmax0, __shfl_xor_sync(0xffffffffu, rmax0, 1));
        rmax0 = fmaxf(rmax0, __shfl_xor_sync(0xffffffffu, rmax0, 2));
        rmax1 = fmaxf(rmax1, __shfl_xor_sync(0xffffffffu, rmax1, 1));
        rmax1 = fmaxf(rmax1, __shfl_xor_sync(0xffffffffu, rmax1, 2));

        float mnew0 = fmaxf(mrow0, rmax0);
        float mnew1 = fmaxf(mrow1, rmax1);
        float alpha0 = __expf(mrow0 - mnew0);
        float alpha1 = __expf(mrow1 - mnew1);

        float rs0 = 0.f, rs1 = 0.f;
#pragma unroll
        for (int nt = 0; nt < 8; nt++) {
            float p0 = __expf(sacc[nt][0] - mnew0);
            float p1 = __expf(sacc[nt][1] - mnew0);
            float p2 = __expf(sacc[nt][2] - mnew1);
            float p3 = __expf(sacc[nt][3] - mnew1);
            rs0 += p0 + p1;
            rs1 += p2 + p3;
            int w = ((nt & 1) << 2) | tig;
            int pos = ((nt >> 1) << 3) | permc(w);
            Ps[(rowbase + g) * ASTR + pos]     = packh2(p0, p1);
            Ps[(rowbase + 8 + g) * ASTR + pos] = packh2(p2, p3);
            Oa[nt][0] *= alpha0; Oa[nt][1] *= alpha0;
            Oa[nt][2] *= alpha1; Oa[nt][3] *= alpha1;
        }
        rs0 += __shfl_xor_sync(0xffffffffu, rs0, 1);
        rs0 += __shfl_xor_sync(0xffffffffu, rs0, 2);
        rs1 += __shfl_xor_sync(0xffffffffu, rs1, 1);
        rs1 += __shfl_xor_sync(0xffffffffu, rs1, 2);
        lrow0 = lrow0 * alpha0 + rs0;
        lrow1 = lrow1 * alpha1 + rs1;
        mrow0 = mnew0; mrow1 = mnew1;

        __syncwarp();  // warp reads only its own P rows

        // O += P V  (64 k-positions -> 4 k16 steps)
#pragma unroll
        for (int step = 0; step < 4; step++) {
            const int kb = step * 8;
            uint2 a02 = *(const uint2*)(Ps + (rowbase + g) * ASTR + kb + 2 * tig);
            uint2 a13 = *(const uint2*)(Ps + (rowbase + 8 + g) * ASTR + kb + 2 * tig);
#pragma unroll
            for (int nt = 0; nt < 8; nt++) {
                uint2 bb = *(const uint2*)(Vt + (nt * 8 + g) * ASTR + kb + 2 * tig);
                mma16(Oa[nt][0], Oa[nt][1], Oa[nt][2], Oa[nt][3],
                      a02.x, a13.x, a02.y, a13.y, bb.x, bb.y);
            }
        }
    }

    // normalize + store [B,S,H*Dh]
    float inv0 = 1.f / lrow0;
    float inv1 = 1.f / lrow1;
    float* o0 = out + ((size_t)(b * SEQ + qrow0)) * DMODEL + h * HDIM;
    float* o1 = out + ((size_t)(b * SEQ + qrow1)) * DMODEL + h * HDIM;
#pragma unroll
    for (int nt = 0; nt < 8; nt++) {
        int dh = nt * 8 + tig * 2;
        *(float2*)(o0 + dh) = make_float2(Oa[nt][0] * inv0, Oa[nt][1] * inv0);
        *(float2*)(o1 + dh) = make_float2(Oa[nt][2] * inv1, Oa[nt][3] * inv1);
    }
}

// ---------------------------------------------------------------------------
// Launch
// ---------------------------------------------------------------------------
extern "C" void kernel_launch(void* const* d_in, const int* in_sizes, int n_in,
                              void* d_out, int out_size) {
    (void)in_sizes; (void)n_in; (void)out_size;
    const float* x  = (const float*)d_in[0];
    const float* Wq = (const float*)d_in[1];
    const float* bq = (const float*)d_in[2];
    const float* Wk = (const float*)d_in[3];
    const float* bk = (const float*)d_in[4];
    const float* Wv = (const float*)d_in[5];
    const float* bv = (const float*)d_in[6];
    float* out = (float*)d_out;

    pack_x_kernel<<<1024, 256>>>(x);
    pack_w_kernel<<<768, 256>>>(Wq, Wk, Wv);

    dim3 gq(48, 32, 1);
    qkv_h<<<gq, 256>>>(bq, bk, bv);

    cudaFuncSetAttribute(attn_kernel, cudaFuncAttributeMaxDynamicSharedMemorySize,
                         ATT_SMEM_BYTES);
    dim3 ga(16, 16, 2);
    attn_kernel<<<ga, 256, ATT_SMEM_BYTES>>>(out);
}

// round 11
// speedup vs baseline: 3.4102x; 1.2160x over previous
#include <cuda_runtime.h>
#include <cuda_fp16.h>
#include <cstdint>

// ---------------------------------------------------------------------------
//   x [2,2048,1024] f32, Wq/Wk/Wv [1024,1024] f32 ([k][n]), bq/bk/bv [1024]
//   out [2,2048,1024] f32 = causal MHA, 16 heads, head_dim 64,
//   softmax((QK^T + mask)/8)
// fp16 datapath: fp16 (10-bit mantissa) == tf32 precision for these ranges.
// ---------------------------------------------------------------------------

#define NHEADS 16
#define HDIM   64
#define SEQ    2048
#define BATCH  2
#define DMODEL 1024

// fp16 pair-packed scratch (word = __half2 = 2 consecutive elements)
__device__ unsigned g_xh[4096 * 512];            // x  [m][k-words], permuted groups
__device__ unsigned g_wt[3 * 1024 * 512];        // W^T [mat][n][k-words], permuted
__device__ unsigned g_qh[BATCH * NHEADS * SEQ * 32];  // [b,h,s][dh-words], permuted
__device__ unsigned g_kh[BATCH * NHEADS * SEQ * 32];  // permuted
__device__ unsigned g_vh[BATCH * NHEADS * SEQ * 32];  // plain row-major (ldmatrix.trans)

// ---------------------------------------------------------------------------
// helpers — mma.m16n8k16 fp16, thread (g=lane>>2, tig=lane&3):
//   A row: a0=(g,2tig..+1) a1=(g+8,2tig..) a2=(g,2tig+8..) a3=(g+8,2tig+8..)
//   B col: b0=(k 2tig..+1, n g) b1=(k 2tig+8.., n g)
//   C:     c0=(g,2tig) c1=(g,2tig+1) c2=(g+8,2tig) c3=(g+8,2tig+1)
//   => QK C-frag (per nt) IS the PV A-frag k-pair: no smem round-trip for P.
//   Word perm within 8-word group: [0,4,1,5,2,6,3,7] -> (tig,tig+4) adjacent.
// ---------------------------------------------------------------------------
__device__ __forceinline__ int permc(int w) {  // w in [0,8)
    return ((w & 3) << 1) | (w >> 2);
}

__device__ __forceinline__ unsigned packh2(float lo, float hi) {
    __half2 h = __floats2half2_rn(lo, hi);
    return *(unsigned*)&h;
}

__device__ __forceinline__ void mma16(float& d0, float& d1, float& d2, float& d3,
                                      unsigned a0, unsigned a1, unsigned a2, unsigned a3,
                                      unsigned b0, unsigned b1) {
    asm("mma.sync.aligned.m16n8k16.row.col.f32.f16.f16.f32 "
        "{%0,%1,%2,%3},{%4,%5,%6,%7},{%8,%9},{%0,%1,%2,%3};"
        : "+f"(d0), "+f"(d1), "+f"(d2), "+f"(d3)
        : "r"(a0), "r"(a1), "r"(a2), "r"(a3), "r"(b0), "r"(b1));
}

// ldmatrix x4 transposed: 16k x 16n row-major b16 tile -> two B operands
__device__ __forceinline__ void ldmT4(unsigned& r0, unsigned& r1,
                                      unsigned& r2, unsigned& r3, const void* p) {
    unsigned a = (unsigned)__cvta_generic_to_shared(p);
    asm volatile("ldmatrix.sync.aligned.m8n8.x4.trans.shared.b16 {%0,%1,%2,%3}, [%4];"
                 : "=r"(r0), "=r"(r1), "=r"(r2), "=r"(r3) : "r"(a));
}

__device__ __forceinline__ void cp16(void* smem, const void* gmem) {
    unsigned s = (unsigned)__cvta_generic_to_shared(smem);
    asm volatile("cp.async.ca.shared.global [%0], [%1], 16;" :: "r"(s), "l"(gmem));
}
#define CP_COMMIT() asm volatile("cp.async.commit_group;" ::: "memory")

// ---------------------------------------------------------------------------
// Pre-pass: pack x -> fp16 pair-words, permuted within 16-elem groups
// ---------------------------------------------------------------------------
__global__ void pack_x_kernel(const float* __restrict__ x) {
    int idx = blockIdx.x * 256 + threadIdx.x;   // 262144 groups of 16 floats
    const float4* src = (const float4*)x + (size_t)idx * 4;
    float4 f0 = src[0], f1 = src[1], f2 = src[2], f3 = src[3];
    unsigned w0 = packh2(f0.x, f0.y), w1 = packh2(f0.z, f0.w);
    unsigned w2 = packh2(f1.x, f1.y), w3 = packh2(f1.z, f1.w);
    unsigned w4 = packh2(f2.x, f2.y), w5 = packh2(f2.z, f2.w);
    unsigned w6 = packh2(f3.x, f3.y), w7 = packh2(f3.z, f3.w);
    uint4* dst = (uint4*)(g_xh + (size_t)idx * 8);
    dst[0] = make_uint4(w0, w4, w1, w5);   // permuted order [0,4,1,5,2,6,3,7]
    dst[1] = make_uint4(w2, w6, w3, w7);
}

// Pre-pass: pack W^T -> g_wt[mat][n][k-words], pairs along k, permuted
__global__ void pack_w_kernel(const float* __restrict__ Wq,
                              const float* __restrict__ Wk,
                              const float* __restrict__ Wv) {
    int id  = blockIdx.x * 256 + threadIdx.x;   // 196608 = 3 * 1024n * 64grp
    int mat = id >> 16;
    int rem = id & 65535;
    int grp = rem >> 10;
    int n   = rem & 1023;
    const float* W = (mat == 0) ? Wq : ((mat == 1) ? Wk : Wv);
    int k0 = grp * 16;
    float f[16];
#pragma unroll
    for (int j = 0; j < 16; j++) f[j] = W[(size_t)(k0 + j) * DMODEL + n];
    unsigned w[8];
#pragma unroll
    for (int j = 0; j < 8; j++) w[j] = packh2(f[2 * j], f[2 * j + 1]);
    uint4* dst = (uint4*)(g_wt + ((size_t)mat << 19) + (size_t)n * 512 + grp * 8);
    dst[0] = make_uint4(w[0], w[4], w[1], w[5]);
    dst[1] = make_uint4(w[2], w[6], w[3], w[7]);
}

// ---------------------------------------------------------------------------
// Kernel 1: QKV projection, fp16 m16n8k16, cp.async double-buffered
//   grid (48, 32): x = mat*16 + ntile (BN=64), y = m-tile (BM=128), BK=32
//   8 warps 4(M)x2(N), warp tile 32x32
// ---------------------------------------------------------------------------
#define QA_STR 24   // 16 words + 8 pad: frag bank pattern conflict-free
#define QB_STR 24

__global__ __launch_bounds__(256, 3)
void qkv_h(const float* __restrict__ bq, const float* __restrict__ bk,
           const float* __restrict__ bv) {
    __shared__ unsigned As[2][128 * QA_STR];
    __shared__ unsigned Bs[2][64 * QB_STR];

    const int tid  = threadIdx.x;
    const int wid  = tid >> 5;
    const int lane = tid & 31;
    const int g    = lane >> 2;
    const int tig  = lane & 3;

    const int mat = blockIdx.x >> 4;
    const int n0  = (blockIdx.x & 15) * 64;
    const int m0  = blockIdx.y * 128;

    const unsigned* Asrc = g_xh + (size_t)m0 * 512;
    const unsigned* Bsrc = g_wt + ((size_t)mat << 19) + (size_t)n0 * 512;
    const float* bias = (mat == 0) ? bq : ((mat == 1) ? bk : bv);

    const int warpM = (wid & 3) * 32;
    const int warpN = (wid >> 2) * 32;

    float acc[2][4][4];
#pragma unroll
    for (int mt = 0; mt < 2; mt++)
#pragma unroll
        for (int nt = 0; nt < 4; nt++)
#pragma unroll
            for (int j = 0; j < 4; j++) acc[mt][nt][j] = 0.f;

    const int ar0 = tid >> 2, ac0 = (tid & 3) * 4;
    const int ar1 = (tid + 256) >> 2, ac1 = ((tid + 256) & 3) * 4;

    // prologue: stage tile 0
    cp16(&As[0][ar0 * QA_STR + ac0], Asrc + (size_t)ar0 * 512 + ac0);
    cp16(&As[0][ar1 * QA_STR + ac1], Asrc + (size_t)ar1 * 512 + ac1);
    cp16(&Bs[0][ar0 * QB_STR + ac0], Bsrc + (size_t)ar0 * 512 + ac0);
    CP_COMMIT();

    for (int it = 0; it < 32; it++) {
        if (it < 31) {
            int buf = (it + 1) & 1, kw = (it + 1) * 16;
            cp16(&As[buf][ar0 * QA_STR + ac0], Asrc + (size_t)ar0 * 512 + kw + ac0);
            cp16(&As[buf][ar1 * QA_STR + ac1], Asrc + (size_t)ar1 * 512 + kw + ac1);
            cp16(&Bs[buf][ar0 * QB_STR + ac0], Bsrc + (size_t)ar0 * 512 + kw + ac0);
            CP_COMMIT();
            asm volatile("cp.async.wait_group 1;" ::: "memory");
        } else {
            asm volatile("cp.async.wait_group 0;" ::: "memory");
        }
        __syncthreads();

        const unsigned* A = As[it & 1];
        const unsigned* B = Bs[it & 1];
#pragma unroll
        for (int step = 0; step < 2; step++) {
            const int kb = step * 8;
            uint2 a02[2], a13[2];
#pragma unroll
            for (int mt = 0; mt < 2; mt++) {
                int row = warpM + mt * 16 + g;
                a02[mt] = *(const uint2*)(A + row * QA_STR + kb + 2 * tig);
                a13[mt] = *(const uint2*)(A + (row + 8) * QA_STR + kb + 2 * tig);
            }
            uint2 bb[4];
#pragma unroll
            for (int nt = 0; nt < 4; nt++)
                bb[nt] = *(const uint2*)(B + (warpN + nt * 8 + g) * QB_STR + kb + 2 * tig);
#pragma unroll
            for (int mt = 0; mt < 2; mt++)
#pragma unroll
                for (int nt = 0; nt < 4; nt++)
                    mma16(acc[mt][nt][0], acc[mt][nt][1], acc[mt][nt][2], acc[mt][nt][3],
                          a02[mt].x, a13[mt].x, a02[mt].y, a13[mt].y, bb[nt].x, bb[nt].y);
        }
        __syncthreads();
    }

    // epilogue: +bias, pack fp16 pairs, scatter to [B,H,S][dh-words]
    unsigned* dst = (mat == 0) ? g_qh : ((mat == 1) ? g_kh : g_vh);
    const bool doperm = (mat != 2);   // V stays plain row-major for ldmatrix.trans
#pragma unroll
    for (int mt = 0; mt < 2; mt++) {
        int r0 = m0 + warpM + mt * 16 + g;
        int r1 = r0 + 8;
        int bb_ = r0 >> 11;
        int s0 = r0 & 2047, s1 = r1 & 2047;
#pragma unroll
        for (int nt = 0; nt < 4; nt++) {
            int col = n0 + warpN + nt * 8 + tig * 2;
            float bv0 = bias[col], bv1 = bias[col + 1];
            int w = (col & 63) >> 1;
            int pos = doperm ? ((w & ~7) | permc(w & 7)) : w;
            int hh = col >> 6;
            size_t base = (size_t)(bb_ * NHEADS + hh) * SEQ;
            dst[(base + s0) * 32 + pos] = packh2(acc[mt][nt][0] + bv0, acc[mt][nt][1] + bv1);
            dst[(base + s1) * 32 + pos] = packh2(acc[mt][nt][2] + bv0, acc[mt][nt][3] + bv1);
        }
    }
}

// ---------------------------------------------------------------------------
// Kernel 2: causal flash attention, fp16 m16n8k16
//   grid (32, 16, 2): x = q-tile of 64 rows (long first), y = head, z = batch
//   block 128 (4 warps), 4 CTAs/SM. Warp w owns q-rows [w*16, w*16+16).
//   K/V double-buffered via cp.async. P kept in registers (C-frag == A-frag).
//   V consumed straight from row-major smem via ldmatrix.x4.trans.
// ---------------------------------------------------------------------------
#define KSTRD 40   // K/Q stride: frag pattern conflict-free
#define VSTRD 36   // V stride: ldmatrix rows 4r mod 32 distinct -> CF
#define KBUF  (64 * KSTRD)
#define VBUF  (64 * VSTRD)
#define ATT_SMEM_WORDS (64 * KSTRD + 2 * KBUF + 2 * VBUF)
#define ATT_SMEM_BYTES (ATT_SMEM_WORDS * 4)

__global__ __launch_bounds__(128, 4)
void attn_kernel(float* __restrict__ out) {
    extern __shared__ unsigned smem[];
    unsigned* Qs = smem;                 // [64][KSTRD] permuted dh-pair words
    unsigned* Ks = Qs + 64 * KSTRD;      // 2 x [64][KSTRD] permuted
    unsigned* Vs = Ks + 2 * KBUF;        // 2 x [64][VSTRD] plain row-major

    const int tid  = threadIdx.x;
    const int wid  = tid >> 5;
    const int lane = tid & 31;
    const int g    = lane >> 2;
    const int tig  = lane & 3;

    const int b  = blockIdx.z;
    const int h  = blockIdx.y;
    const int qt = (int)gridDim.x - 1 - (int)blockIdx.x;  // long tiles first
    const int q0 = qt * 64;

    const size_t hw = (size_t)(b * NHEADS + h) * SEQ * 32;
    const unsigned* gq = g_qh + hw;
    const unsigned* gk = g_kh + hw;
    const unsigned* gv = g_vh + hw;

    const int nkt = qt + 1;

    // prefetch K/V tile 0 (async)
#pragma unroll
    for (int i = 0; i < 4; i++) {
        int id = tid + i * 128;
        int r = id >> 3, c = (id & 7) * 4;
        cp16(Ks + r * KSTRD + c, gk + (size_t)r * 32 + c);
        cp16(Vs + r * VSTRD + c, gv + (size_t)r * 32 + c);
    }
    CP_COMMIT();

    // stage Q tile 64x64 (already packed+permuted)
#pragma unroll
    for (int i = 0; i < 4; i++) {
        int id = tid + i * 128;
        int r = id >> 3, c = (id & 7) * 4;
        *(uint4*)(Qs + r * KSTRD + c) = *(const uint4*)(gq + (size_t)(q0 + r) * 32 + c);
    }

    float Oa[8][4];
#pragma unroll
    for (int nt = 0; nt < 8; nt++)
#pragma unroll
        for (int j = 0; j < 4; j++) Oa[nt][j] = 0.f;

    float mrow0 = -1e30f, mrow1 = -1e30f, lrow0 = 0.f, lrow1 = 0.f;
    const int rowbase = wid * 16;
    const int qrow0 = q0 + rowbase + g;
    const int qrow1 = qrow0 + 8;

    // ldmatrix lane base inside V buffer: rows (lane&15), 16B col (lane>>4)
    const int vlb = (lane & 15) * VSTRD + ((lane >> 4) << 2);

    for (int kt = 0; kt < nkt; kt++) {
        const unsigned* K = Ks + (kt & 1) * KBUF;
        const unsigned* V = Vs + (kt & 1) * VBUF;
        if (kt + 1 < nkt) {
            const int nb = (kt + 1) & 1;
            const size_t kb0 = (size_t)(kt + 1) * 64;
#pragma unroll
            for (int i = 0; i < 4; i++) {
                int id = tid + i * 128;
                int r = id >> 3, c = (id & 7) * 4;
                cp16(Ks + nb * KBUF + r * KSTRD + c, gk + (kb0 + r) * 32 + c);
                cp16(Vs + nb * VBUF + r * VSTRD + c, gv + (kb0 + r) * 32 + c);
            }
            CP_COMMIT();
            asm volatile("cp.async.wait_group 1;" ::: "memory");
        } else {
            asm volatile("cp.async.wait_group 0;" ::: "memory");
        }
        __syncthreads();

        const int kbase = kt * 64;

        // S = Q K^T (Dh=64 -> 4 k16 steps)
        float sacc[8][4];
#pragma unroll
        for (int nt = 0; nt < 8; nt++) {
            sacc[nt][0] = 0.f; sacc[nt][1] = 0.f; sacc[nt][2] = 0.f; sacc[nt][3] = 0.f;
        }
#pragma unroll
        for (int s = 0; s < 4; s++) {
            const int kb = s * 8;
            uint2 a02 = *(const uint2*)(Qs + (rowbase + g) * KSTRD + kb + 2 * tig);
            uint2 a13 = *(const uint2*)(Qs + (rowbase + 8 + g) * KSTRD + kb + 2 * tig);
#pragma unroll
            for (int nt = 0; nt < 8; nt++) {
                uint2 bb = *(const uint2*)(K + (nt * 8 + g) * KSTRD + kb + 2 * tig);
                mma16(sacc[nt][0], sacc[nt][1], sacc[nt][2], sacc[nt][3],
                      a02.x, a13.x, a02.y, a13.y, bb.x, bb.y);
            }
        }

        // logits = (S + mask)/8, online softmax; exp'd P stays in sacc (registers)
        float rmax0 = -1e30f, rmax1 = -1e30f;
#pragma unroll
        for (int nt = 0; nt < 8; nt++) {
            int c0 = kbase + nt * 8 + tig * 2;
            float v0 = sacc[nt][0] * 0.125f + ((c0     > qrow0) ? -1.25e8f : 0.f);
            float v1 = sacc[nt][1] * 0.125f + ((c0 + 1 > qrow0) ? -1.25e8f : 0.f);
            float v2 = sacc[nt][2] * 0.125f + ((c0     > qrow1) ? -1.25e8f : 0.f);
            float v3 = sacc[nt][3] * 0.125f + ((c0 + 1 > qrow1) ? -1.25e8f : 0.f);
            sacc[nt][0] = v0; sacc[nt][1] = v1; sacc[nt][2] = v2; sacc[nt][3] = v3;
            rmax0 = fmaxf(rmax0, fmaxf(v0, v1));
            rmax1 = fmaxf(rmax1, fmaxf(v2, v3));
        }
        rmax0 = fmaxf(rmax0, __shfl_xor_sync(0xffffffffu, rmax0, 1));
        rmax0 = fmaxf(rmax0, __shfl_xor_sync(0xffffffffu, rmax0, 2));
        rmax1 = fmaxf(rmax1, __shfl_xor_sync(0xffffffffu, rmax1, 1));
        rmax1 = fmaxf(rmax1, __shfl_xor_sync(0xffffffffu, rmax1, 2));

        float mnew0 = fmaxf(mrow0, rmax0);
        float mnew1 = fmaxf(mrow1, rmax1);
        float alpha0 = __expf(mrow0 - mnew0);
        float alpha1 = __expf(mrow1 - mnew1);

        float rs0 = 0.f, rs1 = 0.f;
#pragma unroll
        for (int nt = 0; nt < 8; nt++) {
            float p0 = __expf(sacc[nt][0] - mnew0);
            float p1 = __expf(sacc[nt][1] - mnew0);
            float p2 = __expf(sacc[nt][2] - mnew1);
            float p3 = __expf(sacc[nt][3] - mnew1);
            rs0 += p0 + p1;
            rs1 += p2 + p3;
            sacc[nt][0] = p0; sacc[nt][1] = p1; sacc[nt][2] = p2; sacc[nt][3] = p3;
            Oa[nt][0] *= alpha0; Oa[nt][1] *= alpha0;
            Oa[nt][2] *= alpha1; Oa[nt][3] *= alpha1;
        }
        rs0 += __shfl_xor_sync(0xffffffffu, rs0, 1);
        rs0 += __shfl_xor_sync(0xffffffffu, rs0, 2);
        rs1 += __shfl_xor_sync(0xffffffffu, rs1, 1);
        rs1 += __shfl_xor_sync(0xffffffffu, rs1, 2);
        lrow0 = lrow0 * alpha0 + rs0;
        lrow1 = lrow1 * alpha1 + rs1;
        mrow0 = mnew0; mrow1 = mnew1;

        // O += P V : A-frags packed from registers, B-frags via ldmatrix.trans
#pragma unroll
        for (int s = 0; s < 4; s++) {
            unsigned a0 = packh2(sacc[2 * s][0],     sacc[2 * s][1]);
            unsigned a1 = packh2(sacc[2 * s][2],     sacc[2 * s][3]);
            unsigned a2 = packh2(sacc[2 * s + 1][0], sacc[2 * s + 1][1]);
            unsigned a3 = packh2(sacc[2 * s + 1][2], sacc[2 * s + 1][3]);
            const unsigned* vrow = V + s * 16 * VSTRD + vlb;
#pragma unroll
            for (int ntp = 0; ntp < 4; ntp++) {
                unsigned b0, b1, b2, b3;
                ldmT4(b0, b1, b2, b3, vrow + ntp * 8);
                mma16(Oa[2 * ntp][0],     Oa[2 * ntp][1],     Oa[2 * ntp][2],     Oa[2 * ntp][3],
                      a0, a1, a2, a3, b0, b1);
                mma16(Oa[2 * ntp + 1][0], Oa[2 * ntp + 1][1], Oa[2 * ntp + 1][2], Oa[2 * ntp + 1][3],
                      a0, a1, a2, a3, b2, b3);
            }
        }
        __syncthreads();  // all reads of K/V[kt&1] done before next prefetch overwrites
    }

    // normalize + store [B,S,H*Dh]
    float inv0 = 1.f / lrow0;
    float inv1 = 1.f / lrow1;
    float* o0 = out + ((size_t)(b * SEQ + qrow0)) * DMODEL + h * HDIM;
    float* o1 = out + ((size_t)(b * SEQ + qrow1)) * DMODEL + h * HDIM;
#pragma unroll
    for (int nt = 0; nt < 8; nt++) {
        int dh = nt * 8 + tig * 2;
        *(float2*)(o0 + dh) = make_float2(Oa[nt][0] * inv0, Oa[nt][1] * inv0);
        *(float2*)(o1 + dh) = make_float2(Oa[nt][2] * inv1, Oa[nt][3] * inv1);
    }
}

// ---------------------------------------------------------------------------
// Launch
// ---------------------------------------------------------------------------
extern "C" void kernel_launch(void* const* d_in, const int* in_sizes, int n_in,
                              void* d_out, int out_size) {
    (void)in_sizes; (void)n_in; (void)out_size;
    const float* x  = (const float*)d_in[0];
    const float* Wq = (const float*)d_in[1];
    const float* bq = (const float*)d_in[2];
    const float* Wk = (const float*)d_in[3];
    const float* bk = (const float*)d_in[4];
    const float* Wv = (const float*)d_in[5];
    const float* bv = (const float*)d_in[6];
    float* out = (float*)d_out;

    pack_x_kernel<<<1024, 256>>>(x);
    pack_w_kernel<<<768, 256>>>(Wq, Wk, Wv);

    dim3 gq(48, 32, 1);
    qkv_h<<<gq, 256>>>(bq, bk, bv);

    cudaFuncSetAttribute(attn_kernel, cudaFuncAttributeMaxDynamicSharedMemorySize,
                         ATT_SMEM_BYTES);
    dim3 ga(32, 16, 2);
    attn_kernel<<<ga, 128, ATT_SMEM_BYTES>>>(out);
}